// round 4
// baseline (speedup 1.0000x reference)
#include <cuda_runtime.h>
#include <math.h>

#define D 70
#define NMAX 50000
#define EMAX 800000
#define GG 128

// ---------------- device scratch ----------------
__device__ float g_h[NMAX * D];
__device__ float g_A[NMAX * D];
__device__ float g_B[NMAX * D];
__device__ float g_Dh[NMAX * D];
__device__ float g_Eh[NMAX * D];
__device__ float g_hraw[NMAX * D];
__device__ float g_nd[NMAX * 2 * D];   // interleaved (num,den)
__device__ float g_S[EMAX * D];        // cumulative relu(bn(enew)) (permuted order)
__device__ float g_enew[EMAX * D];     // pre-BN edge activations (permuted order)
__device__ double g_stats[4 * D];      // hsum, hsq, esum, esq
__device__ float g_norm[4 * D];        // mu_h, rstd_h, mu_e, rstd_e
__device__ float g_hg[GG * D];
__device__ float g_cnt[GG];
// CSR / permutation
__device__ int g_cnt_n[NMAX];
__device__ int g_rowoff[NMAX + 1];
__device__ int g_psrc[EMAX];
__device__ int g_pdst[EMAX];
__device__ float g_pef[EMAX];
__device__ float g_psn[EMAX];

__device__ __forceinline__ void red_add_v2(float* addr, float a, float b) {
    asm volatile("red.global.add.v2.f32 [%0], {%1, %2};"
                 :: "l"(addr), "f"(a), "f"(b) : "memory");
}

// ---------------- sort: zero / histogram / scan / scatter ----------------
__global__ void zero_all_kernel(int Nn) {
    int i = blockIdx.x * blockDim.x + threadIdx.x;
    int stride = gridDim.x * blockDim.x;
    for (int idx = i; idx < Nn * 2 * D; idx += stride) g_nd[idx] = 0.f;
    for (int idx = i; idx < Nn; idx += stride) g_cnt_n[idx] = 0;
    if (i < 4 * D) g_stats[i] = 0.0;
}

__global__ void hist_kernel(const int* __restrict__ dst, int E_) {
    int i = blockIdx.x * blockDim.x + threadIdx.x;
    if (i < E_) atomicAdd(&g_cnt_n[dst[i]], 1);
}

__global__ void scan_kernel(int Nn, int E_) {
    __shared__ int s[1024];
    int t = threadIdx.x;
    int chunk = (Nn + 1023) / 1024;
    int begin = t * chunk, end = min(begin + chunk, Nn);
    int sum = 0;
    for (int i = begin; i < end; i++) sum += g_cnt_n[i];
    s[t] = sum;
    __syncthreads();
    for (int off = 1; off < 1024; off <<= 1) {
        int tmp = (t >= off) ? s[t - off] : 0;
        __syncthreads();
        s[t] += tmp;
        __syncthreads();
    }
    int acc = s[t] - sum;
    for (int i = begin; i < end; i++) {
        int c = g_cnt_n[i];
        g_rowoff[i] = acc;
        acc += c;
        g_cnt_n[i] = 0;
    }
    if (t == 0) g_rowoff[Nn] = E_;
}

__global__ void scatter_sort_kernel(const int* __restrict__ src, const int* __restrict__ dst,
                                    const float* __restrict__ ef, const float* __restrict__ sn,
                                    int E_) {
    int i = blockIdx.x * blockDim.x + threadIdx.x;
    if (i < E_) {
        int d = dst[i];
        int pos = g_rowoff[d] + atomicAdd(&g_cnt_n[d], 1);
        g_psrc[pos] = src[i];
        g_pdst[pos] = d;
        g_pef[pos] = ef[i];
        g_psn[pos] = sn[i];
    }
}

// ---------------- fused node kernel: [emb or h-update] + 4 GEMMs ----------------
template <int EMB, int FUSE>
__global__ __launch_bounds__(224) void gemm4_kernel(
    const float* __restrict__ nodes, const float* __restrict__ WembH, const float* __restrict__ bembH,
    const float* __restrict__ WA, const float* __restrict__ bA,
    const float* __restrict__ WB, const float* __restrict__ bB,
    const float* __restrict__ WD, const float* __restrict__ bD,
    const float* __restrict__ WE, const float* __restrict__ bE,
    const float* __restrict__ hgam, const float* __restrict__ hbet, int Nn) {
    constexpr int KK = EMB ? 146 : D;
    extern __shared__ float dsm[];
    float* sW = dsm;              // KK*70 (max)
    float* sX = dsm + KK * D;     // 64*KK
    __shared__ float sb[D];
    __shared__ float sMu[D], sRs[D], sGa[D], sBe[D];
    const int tx = threadIdx.x, ty = threadIdx.y;
    const int tid = ty * 14 + tx;
    const int c0 = tx * 5, r0 = ty * 4;
    const int base = blockIdx.x * 64;
    const int cnt = min(64, Nn - base);

    if (EMB) {
        // stage nodes tile + embedding weights; compute h; write h to g_h and sX
        for (int i = tid; i < KK * D; i += 224) sW[i] = WembH[i];
        if (tid < D) sb[tid] = bembH[tid];
        for (int i = tid; i < cnt * KK; i += 224) sX[i] = nodes[(size_t)base * KK + i];
        if (cnt < 64)
            for (int i = cnt * KK + tid; i < 64 * KK; i += 224) sX[i] = 0.f;
        __syncthreads();
        float acc[4][5];
#pragma unroll
        for (int r = 0; r < 4; r++)
#pragma unroll
            for (int c = 0; c < 5; c++) acc[r][c] = sb[c0 + c];
#pragma unroll 2
        for (int k = 0; k < KK; k++) {
            float w0 = sW[k * D + c0 + 0], w1 = sW[k * D + c0 + 1], w2 = sW[k * D + c0 + 2];
            float w3 = sW[k * D + c0 + 3], w4 = sW[k * D + c0 + 4];
#pragma unroll
            for (int r = 0; r < 4; r++) {
                float xv = sX[(r0 + r) * KK + k];
                acc[r][0] += xv * w0; acc[r][1] += xv * w1; acc[r][2] += xv * w2;
                acc[r][3] += xv * w3; acc[r][4] += xv * w4;
            }
        }
        __syncthreads();   // all reads of sX done before overwrite
#pragma unroll
        for (int r = 0; r < 4; r++) {
            int row = base + r0 + r;
#pragma unroll
            for (int c = 0; c < 5; c++) {
                sX[(r0 + r) * D + c0 + c] = acc[r][c];
                if (row < Nn) g_h[(size_t)row * D + c0 + c] = acc[r][c];
            }
        }
    } else {
        if (FUSE && tid < D) {
            sMu[tid] = g_norm[tid];
            sRs[tid] = g_norm[D + tid];
            sGa[tid] = hgam[tid];
            sBe[tid] = hbet[tid];
        }
        __syncthreads();
        for (int idx = tid; idx < cnt * D; idx += 224) {
            size_t gi = (size_t)base * D + idx;
            float v = g_h[gi];
            if (FUSE) {
                int r = idx / D;
                int c = idx - r * D;
                float hr = g_hraw[gi];
                v += fmaxf((hr - sMu[c]) * sRs[c] * sGa[c] + sBe[c], 0.f);
                g_h[gi] = v;
            }
            sX[idx] = v;
        }
        if (cnt < 64)
            for (int idx = cnt * D + tid; idx < 64 * D; idx += 224) sX[idx] = 0.f;
    }

    const float* Ws[4] = {WA, WB, WD, WE};
    const float* bs[4] = {bA, bB, bD, bE};
    float* outs[4] = {g_A, g_B, g_Dh, g_Eh};

    for (int m = 0; m < 4; m++) {
        __syncthreads();
        for (int i = tid; i < D * D; i += 224) sW[i] = Ws[m][i];
        if (tid < D) sb[tid] = bs[m][tid];
        __syncthreads();

        float acc[4][5];
#pragma unroll
        for (int r = 0; r < 4; r++)
#pragma unroll
            for (int c = 0; c < 5; c++) acc[r][c] = sb[c0 + c];

#pragma unroll 2
        for (int k = 0; k < D; k++) {
            float w0 = sW[k * D + c0 + 0], w1 = sW[k * D + c0 + 1], w2 = sW[k * D + c0 + 2];
            float w3 = sW[k * D + c0 + 3], w4 = sW[k * D + c0 + 4];
#pragma unroll
            for (int r = 0; r < 4; r++) {
                float xv = sX[(r0 + r) * D + k];
                acc[r][0] += xv * w0; acc[r][1] += xv * w1; acc[r][2] += xv * w2;
                acc[r][3] += xv * w3; acc[r][4] += xv * w4;
            }
        }
        float* out = outs[m];
#pragma unroll
        for (int r = 0; r < 4; r++) {
            int row = base + r0 + r;
            if (row < Nn) {
#pragma unroll
                for (int c = 0; c < 5; c++) out[(size_t)row * D + c0 + c] = acc[r][c];
            }
        }
    }
}

// ---------------- layer-0 edge+agg: rank-1 ce, node-centric, no atomics ----------------
__global__ __launch_bounds__(560) void agg0_kernel(
    const float* __restrict__ WembE, const float* __restrict__ bembE,
    const float* __restrict__ WC, const float* __restrict__ bC,
    const float* __restrict__ snorm_n, int Nn) {
    int j = threadIdx.x, ty = threadIdx.y;  // (70, 8)
    __shared__ float su[D], sv[D];
    if (ty == 0) {
        float u = 0.f, v = 0.f;
        for (int k = 0; k < D; k++) {
            float w = WC[k * D + j];
            u += WembE[k] * w;
            v += bembE[k] * w;
        }
        su[j] = u;
        sv[j] = v + bC[j];
    }
    __syncthreads();
    float u = su[j], v = sv[j];
    float lsE = 0.f, lqE = 0.f, lsH = 0.f, lqH = 0.f;
    for (int n = blockIdx.x * 8 + ty; n < Nn; n += gridDim.x * 8) {
        float eh = g_Eh[(size_t)n * D + j];
        int e0 = g_rowoff[n], e1 = g_rowoff[n + 1];
        float num = 0.f, den = 0.f;
        for (int e = e0; e < e1; e++) {
            int s = g_psrc[e];
            float en = g_pef[e] * u + v + g_Dh[(size_t)s * D + j] + eh;
            float sg = 1.f / (1.f + __expf(-en));
            num += g_B[(size_t)s * D + j] * sg;
            den += sg;
            float ens = en * g_psn[e];
            g_enew[(size_t)e * D + j] = ens;
            lsE += ens; lqE += ens * ens;
        }
        size_t idx = (size_t)n * D + j;
        float hv = (g_A[idx] + num / (den + 1e-6f)) * snorm_n[n];
        g_hraw[idx] = hv;
        lsH += hv; lqH += hv * hv;
    }
    __shared__ float s1[8][D];
    s1[ty][j] = lsH; __syncthreads();
    if (ty == 0) { float s = lsH; for (int y = 1; y < 8; y++) s += s1[y][j]; atomicAdd(&g_stats[j], (double)s); }
    __syncthreads();
    s1[ty][j] = lqH; __syncthreads();
    if (ty == 0) { float s = lqH; for (int y = 1; y < 8; y++) s += s1[y][j]; atomicAdd(&g_stats[D + j], (double)s); }
    __syncthreads();
    s1[ty][j] = lsE; __syncthreads();
    if (ty == 0) { float s = lsE; for (int y = 1; y < 8; y++) s += s1[y][j]; atomicAdd(&g_stats[2 * D + j], (double)s); }
    __syncthreads();
    s1[ty][j] = lqE; __syncthreads();
    if (ty == 0) { float s = lqE; for (int y = 1; y < 8; y++) s += s1[y][j]; atomicAdd(&g_stats[3 * D + j], (double)s); }
}

// ---------------- fused edge tile kernel (layers 1..3) ----------------
// Per 128-edge tile: S_new = (FIRST?0:S) + relu(bn(enew_prev)) -> smem (+writeback);
// GEMM ce = S_new@WC + ef*u + v; gather Dh[src]+Eh[dst]; sigmoid; run-length
// segmented (num,den) reduction -> red.v2 into g_nd; enew store + e-stats (unless LAST).
template <int FIRST, int LAST>
__global__ __launch_bounds__(224) void edgetile_kernel(
    const float* __restrict__ WC, const float* __restrict__ bC,
    const float* __restrict__ WembE, const float* __restrict__ bembE,
    const float* __restrict__ egam, const float* __restrict__ ebet, int E_) {
    extern __shared__ __align__(16) float dsm[];
    float* sW = dsm;             // 70*70
    float* sX = dsm + D * D;     // 128*70
    __shared__ float su[D], sv[D], sMu[D], sRs[D], sGa[D], sBe[D];
    __shared__ int sS[128], sT[128];
    __shared__ float sef[128], ssn[128];
    const int tx = threadIdx.x, ty = threadIdx.y;
    const int tid = ty * 14 + tx;
    for (int i = tid; i < D * D; i += 224) sW[i] = WC[i];
    if (tid < D) {
        float u = 0.f, v = 0.f;
        for (int k = 0; k < D; k++) {
            float w = WC[k * D + tid];
            u += WembE[k] * w;
            v += bembE[k] * w;
        }
        su[tid] = u;
        sv[tid] = v + bC[tid];
        sMu[tid] = g_norm[2 * D + tid];
        sRs[tid] = g_norm[3 * D + tid];
        sGa[tid] = egam[tid];
        sBe[tid] = ebet[tid];
    }
    __syncthreads();

    const int c0 = tx * 5, r0 = ty * 8;
    float lsum[5] = {0, 0, 0, 0, 0}, lsq[5] = {0, 0, 0, 0, 0};

    for (int base = blockIdx.x * 128; base < E_; base += gridDim.x * 128) {
        int cnt = min(128, E_ - base);
        for (int idx = tid; idx < cnt * D; idx += 224) {
            size_t gi = (size_t)base * D + idx;
            int r = idx / D;
            int c = idx - r * D;
            float R = fmaxf((g_enew[gi] - sMu[c]) * sRs[c] * sGa[c] + sBe[c], 0.f);
            float Sv = FIRST ? R : (g_S[gi] + R);
            sX[idx] = Sv;
            if (!LAST) g_S[gi] = Sv;
        }
        if (cnt < 128)
            for (int idx = cnt * D + tid; idx < 128 * D; idx += 224) sX[idx] = 0.f;
        for (int i = tid; i < 128; i += 224) {
            if (i < cnt) {
                sS[i] = g_psrc[base + i];
                sT[i] = g_pdst[base + i];
                sef[i] = g_pef[base + i];
                ssn[i] = g_psn[base + i];
            } else {
                sT[i] = -1;
                sef[i] = 0.f;
            }
        }
        __syncthreads();

        float acc[8][5];
#pragma unroll
        for (int r = 0; r < 8; r++) {
            float efv = sef[r0 + r];
#pragma unroll
            for (int c = 0; c < 5; c++) acc[r][c] = sv[c0 + c] + efv * su[c0 + c];
        }

#pragma unroll 2
        for (int k = 0; k < D; k++) {
            float w0 = sW[k * D + c0 + 0], w1 = sW[k * D + c0 + 1], w2 = sW[k * D + c0 + 2];
            float w3 = sW[k * D + c0 + 3], w4 = sW[k * D + c0 + 4];
#pragma unroll
            for (int r = 0; r < 8; r++) {
                float xv = sX[(r0 + r) * D + k];
                acc[r][0] += xv * w0; acc[r][1] += xv * w1; acc[r][2] += xv * w2;
                acc[r][3] += xv * w3; acc[r][4] += xv * w4;
            }
        }

        // gather + gate + run-length segmented reduce
        int curd = -1;
        float an[5] = {0, 0, 0, 0, 0}, ad[5] = {0, 0, 0, 0, 0};
#pragma unroll
        for (int r = 0; r < 8; r++) {
            int row = r0 + r;
            int d = sT[row];
            if (d != curd) {
                if (curd >= 0) {
#pragma unroll
                    for (int c = 0; c < 5; c++)
                        red_add_v2(&g_nd[(size_t)curd * 2 * D + 2 * (c0 + c)], an[c], ad[c]);
                }
                curd = d;
#pragma unroll
                for (int c = 0; c < 5; c++) { an[c] = 0.f; ad[c] = 0.f; }
            }
            if (d >= 0) {
                int s = sS[row];
                const float* dhp = g_Dh + (size_t)s * D + c0;
                const float* ehp = g_Eh + (size_t)d * D + c0;
                const float* bhp = g_B + (size_t)s * D + c0;
                float sn = ssn[row];
#pragma unroll
                for (int c = 0; c < 5; c++) {
                    float en = acc[r][c] + dhp[c] + ehp[c];
                    float sg = 1.f / (1.f + __expf(-en));
                    an[c] += bhp[c] * sg;
                    ad[c] += sg;
                    if (!LAST) {
                        float ens = en * sn;
                        g_enew[(size_t)(base + row) * D + c0 + c] = ens;
                        lsum[c] += ens; lsq[c] += ens * ens;
                    }
                }
            }
        }
        if (curd >= 0) {
#pragma unroll
            for (int c = 0; c < 5; c++)
                red_add_v2(&g_nd[(size_t)curd * 2 * D + 2 * (c0 + c)], an[c], ad[c]);
        }
        __syncthreads();
    }

    if (!LAST) {
        double* dsc = (double*)sX;  // 16*70 doubles
#pragma unroll
        for (int c = 0; c < 5; c++) dsc[ty * D + c0 + c] = (double)lsum[c];
        __syncthreads();
        if (ty == 0) {
#pragma unroll
            for (int c = 0; c < 5; c++) {
                double s = 0;
                for (int y = 0; y < 16; y++) s += dsc[y * D + c0 + c];
                atomicAdd(&g_stats[2 * D + c0 + c], s);
            }
        }
        __syncthreads();
#pragma unroll
        for (int c = 0; c < 5; c++) dsc[ty * D + c0 + c] = (double)lsq[c];
        __syncthreads();
        if (ty == 0) {
#pragma unroll
            for (int c = 0; c < 5; c++) {
                double s = 0;
                for (int y = 0; y < 16; y++) s += dsc[y * D + c0 + c];
                atomicAdd(&g_stats[3 * D + c0 + c], s);
            }
        }
    }
}

// ---------------- hraw = (A + num/(den+eps))*snorm + h-stats, zero g_nd ----------------
__global__ void hcombine_kernel(const float* __restrict__ snorm, int Nn) {
    int j = threadIdx.x, ty = threadIdx.y;  // (70, 8)
    float ls = 0.f, lq = 0.f;
    for (int n = blockIdx.x * 8 + ty; n < Nn; n += gridDim.x * 8) {
        float2* ndp = (float2*)&g_nd[(size_t)n * 2 * D + 2 * j];
        float2 nd = *ndp;
        *ndp = make_float2(0.f, 0.f);
        size_t idx = (size_t)n * D + j;
        float v = (g_A[idx] + nd.x / (nd.y + 1e-6f)) * snorm[n];
        g_hraw[idx] = v;
        ls += v; lq += v * v;
    }
    __shared__ float s1[8][D];
    s1[ty][j] = ls; __syncthreads();
    if (ty == 0) { float s = ls; for (int y = 1; y < 8; y++) s += s1[y][j]; atomicAdd(&g_stats[j], (double)s); }
    __syncthreads();
    s1[ty][j] = lq; __syncthreads();
    if (ty == 0) { float s = lq; for (int y = 1; y < 8; y++) s += s1[y][j]; atomicAdd(&g_stats[D + j], (double)s); }
}

__global__ void finalize_kernel(int Nn, int E_) {
    int j = threadIdx.x;
    if (j < D) {
        double mu = g_stats[j] / Nn;
        double var = g_stats[D + j] / Nn - mu * mu;
        g_norm[j] = (float)mu;
        g_norm[D + j] = rsqrtf(fmaxf((float)var, 0.f) + 1e-5f);
        double mue = g_stats[2 * D + j] / E_;
        double vare = g_stats[3 * D + j] / E_ - mue * mue;
        g_norm[2 * D + j] = (float)mue;
        g_norm[3 * D + j] = rsqrtf(fmaxf((float)vare, 0.f) + 1e-5f);
        g_stats[j] = 0.0;
        g_stats[D + j] = 0.0;
        g_stats[2 * D + j] = 0.0;
        g_stats[3 * D + j] = 0.0;
    }
}

// ---------------- readout ----------------
__global__ void zero_readout_kernel() {
    int i = blockIdx.x * blockDim.x + threadIdx.x;
    if (i < GG * D) g_hg[i] = 0.f;
    if (i < GG) g_cnt[i] = 0.f;
}

__global__ void scatter_kernel(const int* __restrict__ gid,
                               const float* __restrict__ hgam, const float* __restrict__ hbet,
                               int Nn) {
    int j = threadIdx.x;
    float mu = g_norm[j], rs = g_norm[D + j], ga = hgam[j], bb = hbet[j];
    for (int row = blockIdx.x * 8 + threadIdx.y; row < Nn; row += gridDim.x * 8) {
        size_t idx = (size_t)row * D + j;
        float v = g_h[idx] + fmaxf((g_hraw[idx] - mu) * rs * ga + bb, 0.f);
        int g = gid[row];
        atomicAdd(&g_hg[g * D + j], v);
        if (j == 0) atomicAdd(&g_cnt[g], 1.f);
    }
}

__global__ void mlp_kernel(const float* __restrict__ W0, const float* __restrict__ b0,
                           const float* __restrict__ W1, const float* __restrict__ b1,
                           const float* __restrict__ W2, const float* __restrict__ b2,
                           float* __restrict__ out) {
    int g = threadIdx.x;
    if (g >= GG) return;
    float cnt = fmaxf(g_cnt[g], 1.f);
    float x[D];
#pragma unroll
    for (int k = 0; k < D; k++) x[k] = g_hg[g * D + k] / cnt;
    float y0[35];
#pragma unroll
    for (int o = 0; o < 35; o++) {
        float s = b0[o];
#pragma unroll
        for (int k = 0; k < D; k++) s += x[k] * W0[k * 35 + o];
        y0[o] = fmaxf(s, 0.f);
    }
    float y1[17];
#pragma unroll
    for (int o = 0; o < 17; o++) {
        float s = b1[o];
#pragma unroll
        for (int k = 0; k < 35; k++) s += y0[k] * W1[k * 17 + o];
        y1[o] = fmaxf(s, 0.f);
    }
#pragma unroll
    for (int o = 0; o < 10; o++) {
        float s = b2[o];
#pragma unroll
        for (int k = 0; k < 17; k++) s += y1[k] * W2[k * 10 + o];
        out[g * 10 + o] = s;
    }
}

// ---------------- host ----------------
extern "C" void kernel_launch(void* const* d_in, const int* in_sizes, int n_in,
                              void* d_out, int out_size) {
    const float* nodes   = (const float*)d_in[0];
    const float* ef      = (const float*)d_in[1];
    const float* snorm_n = (const float*)d_in[2];
    const float* snorm_e = (const float*)d_in[3];
    const int N = in_sizes[2];
    const int E_ = in_sizes[3];

    const int *src, *dst, *gid;
    const float *Wemb_h, *bemb_h, *Wemb_e, *bemb_e;
    const float *WA, *bA, *WB, *bB, *WC, *bC, *WDl, *bDl, *WEl, *bEl;
    const float *gh, *bh, *ge, *be, *W0, *b0, *W1, *b1, *W2, *b2;

    if (in_sizes[4] == E_) {
        src = (const int*)d_in[4]; dst = (const int*)d_in[5]; gid = (const int*)d_in[6];
        Wemb_h = (const float*)d_in[7];  bemb_h = (const float*)d_in[8];
        Wemb_e = (const float*)d_in[9];  bemb_e = (const float*)d_in[10];
        WA = (const float*)d_in[11]; bA = (const float*)d_in[12];
        WB = (const float*)d_in[13]; bB = (const float*)d_in[14];
        WC = (const float*)d_in[15]; bC = (const float*)d_in[16];
        WDl = (const float*)d_in[17]; bDl = (const float*)d_in[18];
        WEl = (const float*)d_in[19]; bEl = (const float*)d_in[20];
        gh = (const float*)d_in[21]; bh = (const float*)d_in[22];
        ge = (const float*)d_in[23]; be = (const float*)d_in[24];
        W0 = (const float*)d_in[25]; b0 = (const float*)d_in[26];
        W1 = (const float*)d_in[27]; b1 = (const float*)d_in[28];
        W2 = (const float*)d_in[29]; b2 = (const float*)d_in[30];
    } else {
        Wemb_h = (const float*)d_in[4];  bemb_h = (const float*)d_in[5];
        Wemb_e = (const float*)d_in[6];  bemb_e = (const float*)d_in[7];
        WA = (const float*)d_in[8];  bA = (const float*)d_in[9];
        WB = (const float*)d_in[10]; bB = (const float*)d_in[11];
        WC = (const float*)d_in[12]; bC = (const float*)d_in[13];
        WDl = (const float*)d_in[14]; bDl = (const float*)d_in[15];
        WEl = (const float*)d_in[16]; bEl = (const float*)d_in[17];
        gh = (const float*)d_in[18]; bh = (const float*)d_in[19];
        ge = (const float*)d_in[20]; be = (const float*)d_in[21];
        W0 = (const float*)d_in[22]; b0 = (const float*)d_in[23];
        W1 = (const float*)d_in[24]; b1 = (const float*)d_in[25];
        W2 = (const float*)d_in[26]; b2 = (const float*)d_in[27];
        src = (const int*)d_in[28]; dst = (const int*)d_in[29]; gid = (const int*)d_in[30];
    }
    float* out = (float*)d_out;

    dim3 tb(14, 16);
    const int gemmBlocks = (N + 63) / 64;
    const size_t smemEmb = (size_t)(146 * D + 64 * 146) * sizeof(float);
    const size_t smemG4  = (size_t)(D * D + 64 * D) * sizeof(float);
    const size_t smemET  = (size_t)(D * D + 128 * D) * sizeof(float);
    cudaFuncSetAttribute(gemm4_kernel<1, 0>, cudaFuncAttributeMaxDynamicSharedMemorySize, (int)smemEmb);
    cudaFuncSetAttribute(gemm4_kernel<0, 1>, cudaFuncAttributeMaxDynamicSharedMemorySize, (int)smemG4);
    cudaFuncSetAttribute(edgetile_kernel<1, 0>, cudaFuncAttributeMaxDynamicSharedMemorySize, (int)smemET);
    cudaFuncSetAttribute(edgetile_kernel<0, 0>, cudaFuncAttributeMaxDynamicSharedMemorySize, (int)smemET);
    cudaFuncSetAttribute(edgetile_kernel<0, 1>, cudaFuncAttributeMaxDynamicSharedMemorySize, (int)smemET);

    const int etBlocks = 444;  // 148 SM * 3

    // 1-3: sort prologue (scatter at 5)
    zero_all_kernel<<<2048, 256>>>(N);
    hist_kernel<<<(E_ + 255) / 256, 256>>>(dst, E_);
    scan_kernel<<<1, 1024>>>(N, E_);
    // 4: fused embedding + layer-0 node GEMMs   <-- profiler capture slot
    gemm4_kernel<1, 0><<<gemmBlocks, tb, smemEmb>>>(nodes, Wemb_h, bemb_h,
        WA, bA, WB, bB, WDl, bDl, WEl, bEl, nullptr, nullptr, N);
    // 5: finish sort
    scatter_sort_kernel<<<(E_ + 255) / 256, 256>>>(src, dst, ef, snorm_e, E_);
    // 6: layer-0 edge + aggregation (rank-1 ce)
    agg0_kernel<<<1024, dim3(D, 8)>>>(Wemb_e, bemb_e, WC, bC, snorm_n, N);
    finalize_kernel<<<1, D>>>(N, E_);

    for (int l = 1; l < 4; l++) {
        const float* wA = WA + l * D * D; const float* biA = bA + l * D;
        const float* wB = WB + l * D * D; const float* biB = bB + l * D;
        const float* wC = WC + l * D * D; const float* biC = bC + l * D;
        const float* wD = WDl + l * D * D; const float* biD = bDl + l * D;
        const float* wE = WEl + l * D * D; const float* biE = bEl + l * D;

        gemm4_kernel<0, 1><<<gemmBlocks, tb, smemG4>>>(nullptr, nullptr, nullptr,
            wA, biA, wB, biB, wD, biD, wE, biE, gh + (l - 1) * D, bh + (l - 1) * D, N);

        const float* eg = ge + (l - 1) * D;
        const float* eb = be + (l - 1) * D;
        if (l == 1)
            edgetile_kernel<1, 0><<<etBlocks, tb, smemET>>>(wC, biC, Wemb_e, bemb_e, eg, eb, E_);
        else if (l == 2)
            edgetile_kernel<0, 0><<<etBlocks, tb, smemET>>>(wC, biC, Wemb_e, bemb_e, eg, eb, E_);
        else
            edgetile_kernel<0, 1><<<etBlocks, tb, smemET>>>(wC, biC, Wemb_e, bemb_e, eg, eb, E_);

        hcombine_kernel<<<1024, dim3(D, 8)>>>(snorm_n, N);
        finalize_kernel<<<1, D>>>(N, E_);
    }

    // readout (final h-update fused into scatter)
    zero_readout_kernel<<<(GG * D + 255) / 256, 256>>>();
    scatter_kernel<<<(N + 7) / 8, dim3(D, 8)>>>(gid, gh + 3 * D, bh + 3 * D, N);
    mlp_kernel<<<1, GG>>>(W0, b0, W1, b1, W2, b2, out);
}

// round 5
// speedup vs baseline: 1.4914x; 1.4914x over previous
#include <cuda_runtime.h>
#include <math.h>

#define D 70
#define NMAX 50000
#define EMAX 800000
#define GG 128

// ---------------- device scratch ----------------
__device__ float g_h[NMAX * D];
__device__ float g_A[NMAX * D];
__device__ float g_B[NMAX * D];
__device__ float g_Dh[NMAX * D];
__device__ float g_Eh[NMAX * D];
__device__ float g_hraw[NMAX * D];
__device__ float g_S[EMAX * D];       // cumulative relu(bn(enew)) (permuted order)
__device__ float g_enew[EMAX * D];    // pre-BN edge activations (permuted order)
__device__ float g_ce[EMAX * D];      // per-layer edge GEMM output (permuted order)
__device__ double g_stats[4 * D];     // hsum, hsq, esum, esq (zeroed by finalize)
__device__ float g_norm[4 * D];       // mu_h, rstd_h, mu_e, rstd_e
__device__ float g_hg[GG * D];
__device__ float g_cnt[GG];
__device__ float g_u[D];              // rank-1 e0 contribution to Ce (per layer)
__device__ float g_v[D];
// CSR / permutation (g_cnt_n starts zero; re-zeroed by agg each layer)
__device__ int g_cnt_n[NMAX];
__device__ int g_rowoff[NMAX + 1];
__device__ int g_psrc[EMAX];
__device__ float g_pef[EMAX];
__device__ float g_psn[EMAX];

// ---------------- sort: histogram / scan / scatter ----------------
__global__ void hist_kernel(const int* __restrict__ dst, int E_) {
    int i = blockIdx.x * blockDim.x + threadIdx.x;
    if (i < E_) atomicAdd(&g_cnt_n[dst[i]], 1);
}

__global__ void scan_kernel(int Nn, int E_) {
    __shared__ int s[1024];
    int t = threadIdx.x;
    int chunk = (Nn + 1023) / 1024;
    int begin = t * chunk, end = min(begin + chunk, Nn);
    int sum = 0;
    for (int i = begin; i < end; i++) sum += g_cnt_n[i];
    s[t] = sum;
    __syncthreads();
    for (int off = 1; off < 1024; off <<= 1) {
        int tmp = (t >= off) ? s[t - off] : 0;
        __syncthreads();
        s[t] += tmp;
        __syncthreads();
    }
    int acc = s[t] - sum;
    for (int i = begin; i < end; i++) {
        int c = g_cnt_n[i];
        g_rowoff[i] = acc;
        acc += c;
        g_cnt_n[i] = 0;  // scatter cursor
    }
    if (t == 0) g_rowoff[Nn] = E_;
}

__global__ void scatter_sort_kernel(const int* __restrict__ src, const int* __restrict__ dst,
                                    const float* __restrict__ ef, const float* __restrict__ sn,
                                    int E_) {
    int i = blockIdx.x * blockDim.x + threadIdx.x;
    if (i < E_) {
        int d = dst[i];
        int pos = g_rowoff[d] + atomicAdd(&g_cnt_n[d], 1);
        g_psrc[pos] = src[i];
        g_pef[pos] = ef[i];
        g_psn[pos] = sn[i];
    }
}

// ---------------- rank-1 layer Ce precompute ----------------
__global__ void uv_kernel(const float* __restrict__ WembE, const float* __restrict__ bembE,
                          const float* __restrict__ WC, const float* __restrict__ bC) {
    int j = threadIdx.x;
    if (j >= D) return;
    float u = 0.f, v = 0.f;
    for (int k = 0; k < D; k++) {
        float w = WC[k * D + j];
        u += WembE[k] * w;
        v += bembE[k] * w;
    }
    g_u[j] = u;
    g_v[j] = v + bC[j];
}

// ---------------- embedding GEMM [N,146]@[146,70] ----------------
template <int K>
__global__ void gemm70_kernel(const float* __restrict__ X, const float* __restrict__ W,
                              const float* __restrict__ bias, float* __restrict__ Y, int M) {
    extern __shared__ float smem[];
    float* sW = smem;
    float* sX = smem + K * D;
    __shared__ float sb[D];
    const int tx = threadIdx.x, ty = threadIdx.y;
    const int tid = ty * 14 + tx;
    for (int i = tid; i < K * D; i += 224) sW[i] = W[i];
    if (tid < D) sb[tid] = bias[tid];
    __syncthreads();

    const int base = blockIdx.x * 64;
    const int cnt = min(64, M - base);
    for (int i = tid; i < cnt * K; i += 224) sX[i] = X[(size_t)base * K + i];
    __syncthreads();

    const int c0 = tx * 5, r0 = ty * 4;
    float acc[4][5];
#pragma unroll
    for (int r = 0; r < 4; r++)
#pragma unroll
        for (int c = 0; c < 5; c++) acc[r][c] = sb[c0 + c];

#pragma unroll 2
    for (int k = 0; k < K; k++) {
        float w0 = sW[k * D + c0 + 0], w1 = sW[k * D + c0 + 1], w2 = sW[k * D + c0 + 2];
        float w3 = sW[k * D + c0 + 3], w4 = sW[k * D + c0 + 4];
#pragma unroll
        for (int r = 0; r < 4; r++) {
            float xv = (r0 + r < cnt) ? sX[(r0 + r) * K + k] : 0.f;
            acc[r][0] += xv * w0; acc[r][1] += xv * w1; acc[r][2] += xv * w2;
            acc[r][3] += xv * w3; acc[r][4] += xv * w4;
        }
    }
#pragma unroll
    for (int r = 0; r < 4; r++) {
        int row = base + r0 + r;
        if (row < M) {
#pragma unroll
            for (int c = 0; c < 5; c++) Y[(size_t)row * D + c0 + c] = acc[r][c];
        }
    }
}

// ---------------- fused node kernel: optional h-update + 4 GEMMs ----------------
__global__ __launch_bounds__(224) void gemm4_kernel(
    const float* __restrict__ WA, const float* __restrict__ bA,
    const float* __restrict__ WB, const float* __restrict__ bB,
    const float* __restrict__ WD, const float* __restrict__ bD,
    const float* __restrict__ WE, const float* __restrict__ bE,
    const float* __restrict__ hgam, const float* __restrict__ hbet,
    int fuse, int Nn) {
    __shared__ float sX[64 * D];
    __shared__ float sW[D * D];
    __shared__ float sb[D];
    __shared__ float sMu[D], sRs[D], sGa[D], sBe[D];
    const int tx = threadIdx.x, ty = threadIdx.y;
    const int tid = ty * 14 + tx;
    if (fuse && tid < D) {
        sMu[tid] = g_norm[tid];
        sRs[tid] = g_norm[D + tid];
        sGa[tid] = hgam[tid];
        sBe[tid] = hbet[tid];
    }
    const int base = blockIdx.x * 64;
    const int cnt = min(64, Nn - base);
    __syncthreads();
    for (int idx = tid; idx < cnt * D; idx += 224) {
        size_t gi = (size_t)base * D + idx;
        float v = g_h[gi];
        if (fuse) {
            int r = idx / D;
            int c = idx - r * D;
            float hr = g_hraw[gi];
            v += fmaxf((hr - sMu[c]) * sRs[c] * sGa[c] + sBe[c], 0.f);
            g_h[gi] = v;
        }
        sX[idx] = v;
    }
    if (cnt < 64)
        for (int idx = cnt * D + tid; idx < 64 * D; idx += 224) sX[idx] = 0.f;

    const float* Ws[4] = {WA, WB, WD, WE};
    const float* bs[4] = {bA, bB, bD, bE};
    float* outs[4] = {g_A, g_B, g_Dh, g_Eh};

    const int c0 = tx * 5, r0 = ty * 4;
    for (int m = 0; m < 4; m++) {
        __syncthreads();
        for (int i = tid; i < D * D; i += 224) sW[i] = Ws[m][i];
        if (tid < D) sb[tid] = bs[m][tid];
        __syncthreads();

        float acc[4][5];
#pragma unroll
        for (int r = 0; r < 4; r++)
#pragma unroll
            for (int c = 0; c < 5; c++) acc[r][c] = sb[c0 + c];

#pragma unroll 2
        for (int k = 0; k < D; k++) {
            float w0 = sW[k * D + c0 + 0], w1 = sW[k * D + c0 + 1], w2 = sW[k * D + c0 + 2];
            float w3 = sW[k * D + c0 + 3], w4 = sW[k * D + c0 + 4];
#pragma unroll
            for (int r = 0; r < 4; r++) {
                float xv = sX[(r0 + r) * D + k];
                acc[r][0] += xv * w0; acc[r][1] += xv * w1; acc[r][2] += xv * w2;
                acc[r][3] += xv * w3; acc[r][4] += xv * w4;
            }
        }
        float* out = outs[m];
#pragma unroll
        for (int r = 0; r < 4; r++) {
            int row = base + r0 + r;
            if (row < Nn) {
#pragma unroll
                for (int c = 0; c < 5; c++) out[(size_t)row * D + c0 + c] = acc[r][c];
            }
        }
    }
}

// ---------------- streaming edge GEMM: ce = S_new@WC + ef*u + v ----------------
template <int FIRST, int WRITE_S>
__global__ __launch_bounds__(224) void edgegemm_kernel(
    const float* __restrict__ WC,
    const float* __restrict__ egam, const float* __restrict__ ebet, int E_) {
    extern __shared__ __align__(16) float dsm[];
    float* sW = dsm;             // 70*70
    float* sX = dsm + D * D;     // 128*70
    __shared__ float sef[128];
    __shared__ float su[D], sv[D], sMu[D], sRs[D], sGa[D], sBe[D];
    const int tx = threadIdx.x, ty = threadIdx.y;
    const int tid = ty * 14 + tx;
    for (int i = tid; i < D * D; i += 224) sW[i] = WC[i];
    if (tid < D) {
        su[tid] = g_u[tid];
        sv[tid] = g_v[tid];
        sMu[tid] = g_norm[2 * D + tid];
        sRs[tid] = g_norm[3 * D + tid];
        sGa[tid] = egam[tid];
        sBe[tid] = ebet[tid];
    }
    __syncthreads();

    const int base = blockIdx.x * 128;
    const int cnt = min(128, E_ - base);
    for (int idx = tid; idx < cnt * D; idx += 224) {
        size_t gi = (size_t)base * D + idx;
        int r = idx / D;
        int c = idx - r * D;
        float R = fmaxf((g_enew[gi] - sMu[c]) * sRs[c] * sGa[c] + sBe[c], 0.f);
        float Sv = FIRST ? R : (g_S[gi] + R);
        sX[idx] = Sv;
        if (WRITE_S) g_S[gi] = Sv;
    }
    if (cnt < 128)
        for (int idx = cnt * D + tid; idx < 128 * D; idx += 224) sX[idx] = 0.f;
    for (int i = tid; i < 128; i += 224) sef[i] = (i < cnt) ? g_pef[base + i] : 0.f;
    __syncthreads();

    const int c0 = tx * 5, r0 = ty * 8;
    float acc[8][5];
#pragma unroll
    for (int r = 0; r < 8; r++) {
        float efv = sef[r0 + r];
#pragma unroll
        for (int c = 0; c < 5; c++) acc[r][c] = sv[c0 + c] + efv * su[c0 + c];
    }

#pragma unroll 2
    for (int k = 0; k < D; k++) {
        float w0 = sW[k * D + c0 + 0], w1 = sW[k * D + c0 + 1], w2 = sW[k * D + c0 + 2];
        float w3 = sW[k * D + c0 + 3], w4 = sW[k * D + c0 + 4];
#pragma unroll
        for (int r = 0; r < 8; r++) {
            float xv = sX[(r0 + r) * D + k];
            acc[r][0] += xv * w0; acc[r][1] += xv * w1; acc[r][2] += xv * w2;
            acc[r][3] += xv * w3; acc[r][4] += xv * w4;
        }
    }
#pragma unroll
    for (int r = 0; r < 8; r++) {
        int ei = base + r0 + r;
        if (ei < E_) {
#pragma unroll
            for (int c = 0; c < 5; c++) g_ce[(size_t)ei * D + c0 + c] = acc[r][c];
        }
    }
}

// ---------------- node-centric aggregation (no atomics, full parallel, unroll-2) ----------------
template <int RANK1, int LAST>
__global__ __launch_bounds__(560) void agg_kernel(const float* __restrict__ snorm_n, int Nn) {
    const int j = threadIdx.x, ty = threadIdx.y;  // (70, 8); one node per (block,ty)
    // reset histogram counters for the next graph replay (idempotent)
    for (int i = blockIdx.x * 560 + ty * D + j; i < Nn; i += gridDim.x * 560) g_cnt_n[i] = 0;

    const float u = g_u[j], v = g_v[j];
    float lsE = 0.f, lqE = 0.f, lsH = 0.f, lqH = 0.f;
    const int n = blockIdx.x * 8 + ty;
    if (n < Nn) {
        const float eh = g_Eh[(size_t)n * D + j];
        const int e0 = g_rowoff[n], e1 = g_rowoff[n + 1];
        float num = 0.f, den = 0.f, num2 = 0.f, den2 = 0.f;
        int e = e0;
        for (; e + 2 <= e1; e += 2) {
            int s0 = g_psrc[e], s1 = g_psrc[e + 1];
            float ce0, ce1;
            if (RANK1) {
                ce0 = g_pef[e] * u + v;
                ce1 = g_pef[e + 1] * u + v;
            } else {
                ce0 = g_ce[(size_t)e * D + j];
                ce1 = g_ce[(size_t)(e + 1) * D + j];
            }
            float dh0 = g_Dh[(size_t)s0 * D + j], dh1 = g_Dh[(size_t)s1 * D + j];
            float bb0 = g_B[(size_t)s0 * D + j],  bb1 = g_B[(size_t)s1 * D + j];
            float en0 = ce0 + dh0 + eh, en1 = ce1 + dh1 + eh;
            float sg0 = 1.f / (1.f + __expf(-en0));
            float sg1 = 1.f / (1.f + __expf(-en1));
            num += bb0 * sg0;  den += sg0;
            num2 += bb1 * sg1; den2 += sg1;
            if (!LAST) {
                float ens0 = en0 * g_psn[e];
                float ens1 = en1 * g_psn[e + 1];
                g_enew[(size_t)e * D + j] = ens0;
                g_enew[(size_t)(e + 1) * D + j] = ens1;
                lsE += ens0 + ens1;
                lqE += ens0 * ens0 + ens1 * ens1;
            }
        }
        if (e < e1) {
            int s0 = g_psrc[e];
            float ce0 = RANK1 ? (g_pef[e] * u + v) : g_ce[(size_t)e * D + j];
            float en0 = ce0 + g_Dh[(size_t)s0 * D + j] + eh;
            float sg0 = 1.f / (1.f + __expf(-en0));
            num += g_B[(size_t)s0 * D + j] * sg0;
            den += sg0;
            if (!LAST) {
                float ens0 = en0 * g_psn[e];
                g_enew[(size_t)e * D + j] = ens0;
                lsE += ens0;
                lqE += ens0 * ens0;
            }
        }
        num += num2;
        den += den2;
        size_t idx = (size_t)n * D + j;
        float hv = (g_A[idx] + num / (den + 1e-6f)) * snorm_n[n];
        g_hraw[idx] = hv;
        lsH = hv;
        lqH = hv * hv;
    }
    __shared__ float s1[8][D];
    s1[ty][j] = lsH; __syncthreads();
    if (ty == 0) { float s = lsH; for (int y = 1; y < 8; y++) s += s1[y][j]; atomicAdd(&g_stats[j], (double)s); }
    __syncthreads();
    s1[ty][j] = lqH; __syncthreads();
    if (ty == 0) { float s = lqH; for (int y = 1; y < 8; y++) s += s1[y][j]; atomicAdd(&g_stats[D + j], (double)s); }
    if (!LAST) {
        __syncthreads();
        s1[ty][j] = lsE; __syncthreads();
        if (ty == 0) { float s = lsE; for (int y = 1; y < 8; y++) s += s1[y][j]; atomicAdd(&g_stats[2 * D + j], (double)s); }
        __syncthreads();
        s1[ty][j] = lqE; __syncthreads();
        if (ty == 0) { float s = lqE; for (int y = 1; y < 8; y++) s += s1[y][j]; atomicAdd(&g_stats[3 * D + j], (double)s); }
    }
}

__global__ void finalize_kernel(int Nn, int E_) {
    int j = threadIdx.x;
    if (j < D) {
        double mu = g_stats[j] / Nn;
        double var = g_stats[D + j] / Nn - mu * mu;
        g_norm[j] = (float)mu;
        g_norm[D + j] = rsqrtf(fmaxf((float)var, 0.f) + 1e-5f);
        double mue = g_stats[2 * D + j] / E_;
        double vare = g_stats[3 * D + j] / E_ - mue * mue;
        g_norm[2 * D + j] = (float)mue;
        g_norm[3 * D + j] = rsqrtf(fmaxf((float)vare, 0.f) + 1e-5f);
        g_stats[j] = 0.0;
        g_stats[D + j] = 0.0;
        g_stats[2 * D + j] = 0.0;
        g_stats[3 * D + j] = 0.0;
    }
}

// ---------------- readout ----------------
__global__ void zero_readout_kernel() {
    int i = blockIdx.x * blockDim.x + threadIdx.x;
    if (i < GG * D) g_hg[i] = 0.f;
    if (i < GG) g_cnt[i] = 0.f;
}

__global__ void scatter_kernel(const int* __restrict__ gid,
                               const float* __restrict__ hgam, const float* __restrict__ hbet,
                               int Nn) {
    int j = threadIdx.x;
    float mu = g_norm[j], rs = g_norm[D + j], ga = hgam[j], bb = hbet[j];
    for (int row = blockIdx.x * 8 + threadIdx.y; row < Nn; row += gridDim.x * 8) {
        size_t idx = (size_t)row * D + j;
        float v = g_h[idx] + fmaxf((g_hraw[idx] - mu) * rs * ga + bb, 0.f);
        int g = gid[row];
        atomicAdd(&g_hg[g * D + j], v);
        if (j == 0) atomicAdd(&g_cnt[g], 1.f);
    }
}

__global__ void mlp_kernel(const float* __restrict__ W0, const float* __restrict__ b0,
                           const float* __restrict__ W1, const float* __restrict__ b1,
                           const float* __restrict__ W2, const float* __restrict__ b2,
                           float* __restrict__ out) {
    int g = threadIdx.x;
    if (g >= GG) return;
    float cnt = fmaxf(g_cnt[g], 1.f);
    float x[D];
#pragma unroll
    for (int k = 0; k < D; k++) x[k] = g_hg[g * D + k] / cnt;
    float y0[35];
#pragma unroll
    for (int o = 0; o < 35; o++) {
        float s = b0[o];
#pragma unroll
        for (int k = 0; k < D; k++) s += x[k] * W0[k * 35 + o];
        y0[o] = fmaxf(s, 0.f);
    }
    float y1[17];
#pragma unroll
    for (int o = 0; o < 17; o++) {
        float s = b1[o];
#pragma unroll
        for (int k = 0; k < 35; k++) s += y0[k] * W1[k * 17 + o];
        y1[o] = fmaxf(s, 0.f);
    }
#pragma unroll
    for (int o = 0; o < 10; o++) {
        float s = b2[o];
#pragma unroll
        for (int k = 0; k < 17; k++) s += y1[k] * W2[k * 10 + o];
        out[g * 10 + o] = s;
    }
}

// ---------------- host ----------------
extern "C" void kernel_launch(void* const* d_in, const int* in_sizes, int n_in,
                              void* d_out, int out_size) {
    const float* nodes   = (const float*)d_in[0];
    const float* ef      = (const float*)d_in[1];
    const float* snorm_n = (const float*)d_in[2];
    const float* snorm_e = (const float*)d_in[3];
    const int N = in_sizes[2];
    const int E_ = in_sizes[3];

    const int *src, *dst, *gid;
    const float *Wemb_h, *bemb_h, *Wemb_e, *bemb_e;
    const float *WA, *bA, *WB, *bB, *WC, *bC, *WDl, *bDl, *WEl, *bEl;
    const float *gh, *bh, *ge, *be, *W0, *b0, *W1, *b1, *W2, *b2;

    if (in_sizes[4] == E_) {
        src = (const int*)d_in[4]; dst = (const int*)d_in[5]; gid = (const int*)d_in[6];
        Wemb_h = (const float*)d_in[7];  bemb_h = (const float*)d_in[8];
        Wemb_e = (const float*)d_in[9];  bemb_e = (const float*)d_in[10];
        WA = (const float*)d_in[11]; bA = (const float*)d_in[12];
        WB = (const float*)d_in[13]; bB = (const float*)d_in[14];
        WC = (const float*)d_in[15]; bC = (const float*)d_in[16];
        WDl = (const float*)d_in[17]; bDl = (const float*)d_in[18];
        WEl = (const float*)d_in[19]; bEl = (const float*)d_in[20];
        gh = (const float*)d_in[21]; bh = (const float*)d_in[22];
        ge = (const float*)d_in[23]; be = (const float*)d_in[24];
        W0 = (const float*)d_in[25]; b0 = (const float*)d_in[26];
        W1 = (const float*)d_in[27]; b1 = (const float*)d_in[28];
        W2 = (const float*)d_in[29]; b2 = (const float*)d_in[30];
    } else {
        Wemb_h = (const float*)d_in[4];  bemb_h = (const float*)d_in[5];
        Wemb_e = (const float*)d_in[6];  bemb_e = (const float*)d_in[7];
        WA = (const float*)d_in[8];  bA = (const float*)d_in[9];
        WB = (const float*)d_in[10]; bB = (const float*)d_in[11];
        WC = (const float*)d_in[12]; bC = (const float*)d_in[13];
        WDl = (const float*)d_in[14]; bDl = (const float*)d_in[15];
        WEl = (const float*)d_in[16]; bEl = (const float*)d_in[17];
        gh = (const float*)d_in[18]; bh = (const float*)d_in[19];
        ge = (const float*)d_in[20]; be = (const float*)d_in[21];
        W0 = (const float*)d_in[22]; b0 = (const float*)d_in[23];
        W1 = (const float*)d_in[24]; b1 = (const float*)d_in[25];
        W2 = (const float*)d_in[26]; b2 = (const float*)d_in[27];
        src = (const int*)d_in[28]; dst = (const int*)d_in[29]; gid = (const int*)d_in[30];
    }
    float* out = (float*)d_out;

    float* ph;
    cudaGetSymbolAddress((void**)&ph, g_h);

    dim3 tb(14, 16);
    const int gemmBlocks = (N + 63) / 64;
    const int aggBlocks = (N + 7) / 8;
    const size_t smem146 = (size_t)(146 * D + 64 * 146) * sizeof(float);
    const size_t smemEG = (size_t)(D * D + 128 * D) * sizeof(float);
    cudaFuncSetAttribute(gemm70_kernel<146>, cudaFuncAttributeMaxDynamicSharedMemorySize, (int)smem146);
    cudaFuncSetAttribute(edgegemm_kernel<1, 1>, cudaFuncAttributeMaxDynamicSharedMemorySize, (int)smemEG);
    cudaFuncSetAttribute(edgegemm_kernel<0, 1>, cudaFuncAttributeMaxDynamicSharedMemorySize, (int)smemEG);
    cudaFuncSetAttribute(edgegemm_kernel<0, 0>, cudaFuncAttributeMaxDynamicSharedMemorySize, (int)smemEG);

    const int egBlocks = (E_ + 127) / 128;

    // interleave sort and layer-0 node path (gemm4 lands in profiler slot #4)
    hist_kernel<<<(E_ + 255) / 256, 256>>>(dst, E_);                                    // 1
    gemm70_kernel<146><<<gemmBlocks, tb, smem146>>>(nodes, Wemb_h, bemb_h, ph, N);      // 2
    scan_kernel<<<1, 1024>>>(N, E_);                                                    // 3
    gemm4_kernel<<<gemmBlocks, tb>>>(WA, bA, WB, bB, WDl, bDl, WEl, bEl,                // 4
                                     nullptr, nullptr, 0, N);
    scatter_sort_kernel<<<(E_ + 255) / 256, 256>>>(src, dst, ef, snorm_e, E_);          // 5
    uv_kernel<<<1, D>>>(Wemb_e, bemb_e, WC, bC);                                        // 6
    agg_kernel<1, 0><<<aggBlocks, dim3(D, 8)>>>(snorm_n, N);                            // 7
    finalize_kernel<<<1, D>>>(N, E_);                                                   // 8

    for (int l = 1; l < 4; l++) {
        const float* wA = WA + l * D * D; const float* biA = bA + l * D;
        const float* wB = WB + l * D * D; const float* biB = bB + l * D;
        const float* wC = WC + l * D * D; const float* biC = bC + l * D;
        const float* wD = WDl + l * D * D; const float* biD = bDl + l * D;
        const float* wE = WEl + l * D * D; const float* biE = bEl + l * D;

        uv_kernel<<<1, D>>>(Wemb_e, bemb_e, wC, biC);
        gemm4_kernel<<<gemmBlocks, tb>>>(wA, biA, wB, biB, wD, biD, wE, biE,
                                         gh + (l - 1) * D, bh + (l - 1) * D, 1, N);

        const float* eg = ge + (l - 1) * D;
        const float* eb = be + (l - 1) * D;
        if (l == 1)
            edgegemm_kernel<1, 1><<<egBlocks, tb, smemEG>>>(wC, eg, eb, E_);
        else if (l == 2)
            edgegemm_kernel<0, 1><<<egBlocks, tb, smemEG>>>(wC, eg, eb, E_);
        else
            edgegemm_kernel<0, 0><<<egBlocks, tb, smemEG>>>(wC, eg, eb, E_);

        if (l == 3)
            agg_kernel<0, 1><<<aggBlocks, dim3(D, 8)>>>(snorm_n, N);
        else
            agg_kernel<0, 0><<<aggBlocks, dim3(D, 8)>>>(snorm_n, N);
        finalize_kernel<<<1, D>>>(N, E_);
    }

    // readout (final h-update fused into scatter)
    zero_readout_kernel<<<(GG * D + 255) / 256, 256>>>();
    scatter_kernel<<<(N + 7) / 8, dim3(D, 8)>>>(gid, gh + 3 * D, bh + 3 * D, N);
    mlp_kernel<<<1, GG>>>(W0, b0, W1, b1, W2, b2, out);
}

// round 6
// speedup vs baseline: 1.5634x; 1.0483x over previous
#include <cuda_runtime.h>
#include <math.h>

#define D 70
#define NMAX 50000
#define EMAX 800000
#define GG 128

// ---------------- device scratch ----------------
__device__ float g_h[NMAX * D];
__device__ float g_A[NMAX * D];
__device__ float g_B[NMAX * D];
__device__ float g_Dh[NMAX * D];
__device__ float g_Eh[NMAX * D];
__device__ float g_hraw[NMAX * D];
__device__ float g_S[EMAX * D];       // cumulative relu(bn(enew)) (permuted order)
__device__ float g_enew[EMAX * D];    // pre-BN edge activations (permuted order)
__device__ float g_ce[EMAX * D];      // per-layer edge GEMM output (permuted order)
__device__ float g_statsf[4][64][D];  // sharded BN-stat partials (zeroed by finalize)
__device__ float g_norm[4 * D];       // mu_h, rstd_h, mu_e, rstd_e
__device__ float g_hg[GG * D];
__device__ float g_cnt[GG];
__device__ float g_u[D];              // rank-1 e0 contribution to Ce (per layer)
__device__ float g_v[D];
// CSR / permutation (g_cnt_n zero at start; re-zeroed by agg each layer)
__device__ int g_cnt_n[NMAX];
__device__ int g_rowoff[NMAX + 1];
__device__ int g_psrc[EMAX];
__device__ float g_pef[EMAX];
__device__ float g_psn[EMAX];

// ---------------- sort: histogram / scan / scatter ----------------
__global__ void hist_kernel(const int* __restrict__ dst, int E_) {
    int i = blockIdx.x * blockDim.x + threadIdx.x;
    if (i < E_) atomicAdd(&g_cnt_n[dst[i]], 1);
}

__global__ void scan_kernel(int Nn, int E_) {
    __shared__ int s[1024];
    int t = threadIdx.x;
    int chunk = (Nn + 1023) / 1024;
    int begin = t * chunk, end = min(begin + chunk, Nn);
    int sum = 0;
    for (int i = begin; i < end; i++) sum += g_cnt_n[i];
    s[t] = sum;
    __syncthreads();
    for (int off = 1; off < 1024; off <<= 1) {
        int tmp = (t >= off) ? s[t - off] : 0;
        __syncthreads();
        s[t] += tmp;
        __syncthreads();
    }
    int acc = s[t] - sum;
    for (int i = begin; i < end; i++) {
        int c = g_cnt_n[i];
        g_rowoff[i] = acc;
        acc += c;
        g_cnt_n[i] = 0;  // scatter cursor
    }
    if (t == 0) g_rowoff[Nn] = E_;
}

__global__ void scatter_sort_kernel(const int* __restrict__ src, const int* __restrict__ dst,
                                    const float* __restrict__ ef, const float* __restrict__ sn,
                                    int E_) {
    int i = blockIdx.x * blockDim.x + threadIdx.x;
    if (i < E_) {
        int d = dst[i];
        int pos = g_rowoff[d] + atomicAdd(&g_cnt_n[d], 1);
        g_psrc[pos] = src[i];
        g_pef[pos] = ef[i];
        g_psn[pos] = sn[i];
    }
}

// ---------------- layer-0 rank-1 Ce precompute ----------------
__global__ void uv_kernel(const float* __restrict__ WembE, const float* __restrict__ bembE,
                          const float* __restrict__ WC, const float* __restrict__ bC) {
    int j = threadIdx.x;
    if (j >= D) return;
    float u = 0.f, v = 0.f;
    for (int k = 0; k < D; k++) {
        float w = WC[k * D + j];
        u += WembE[k] * w;
        v += bembE[k] * w;
    }
    g_u[j] = u;
    g_v[j] = v + bC[j];
}

// ---------------- embedding GEMM [N,146]@[146,70] ----------------
template <int K>
__global__ void gemm70_kernel(const float* __restrict__ X, const float* __restrict__ W,
                              const float* __restrict__ bias, float* __restrict__ Y, int M) {
    extern __shared__ float smem[];
    float* sW = smem;
    float* sX = smem + K * D;
    __shared__ float sb[D];
    const int tx = threadIdx.x, ty = threadIdx.y;
    const int tid = ty * 14 + tx;
    for (int i = tid; i < K * D; i += 224) sW[i] = W[i];
    if (tid < D) sb[tid] = bias[tid];
    __syncthreads();

    const int base = blockIdx.x * 64;
    const int cnt = min(64, M - base);
    for (int i = tid; i < cnt * K; i += 224) sX[i] = X[(size_t)base * K + i];
    __syncthreads();

    const int c0 = tx * 5, r0 = ty * 4;
    float acc[4][5];
#pragma unroll
    for (int r = 0; r < 4; r++)
#pragma unroll
        for (int c = 0; c < 5; c++) acc[r][c] = sb[c0 + c];

#pragma unroll 2
    for (int k = 0; k < K; k++) {
        float w0 = sW[k * D + c0 + 0], w1 = sW[k * D + c0 + 1], w2 = sW[k * D + c0 + 2];
        float w3 = sW[k * D + c0 + 3], w4 = sW[k * D + c0 + 4];
#pragma unroll
        for (int r = 0; r < 4; r++) {
            float xv = (r0 + r < cnt) ? sX[(r0 + r) * K + k] : 0.f;
            acc[r][0] += xv * w0; acc[r][1] += xv * w1; acc[r][2] += xv * w2;
            acc[r][3] += xv * w3; acc[r][4] += xv * w4;
        }
    }
#pragma unroll
    for (int r = 0; r < 4; r++) {
        int row = base + r0 + r;
        if (row < M) {
#pragma unroll
            for (int c = 0; c < 5; c++) Y[(size_t)row * D + c0 + c] = acc[r][c];
        }
    }
}

// ---------------- fused node kernel: optional h-update + 4 GEMMs ----------------
__global__ __launch_bounds__(224) void gemm4_kernel(
    const float* __restrict__ WA, const float* __restrict__ bA,
    const float* __restrict__ WB, const float* __restrict__ bB,
    const float* __restrict__ WD, const float* __restrict__ bD,
    const float* __restrict__ WE, const float* __restrict__ bE,
    const float* __restrict__ hgam, const float* __restrict__ hbet,
    int fuse, int Nn) {
    __shared__ float sX[64 * D];
    __shared__ float sW[D * D];
    __shared__ float sb[D];
    __shared__ float sMu[D], sRs[D], sGa[D], sBe[D];
    const int tx = threadIdx.x, ty = threadIdx.y;
    const int tid = ty * 14 + tx;
    if (fuse && tid < D) {
        sMu[tid] = g_norm[tid];
        sRs[tid] = g_norm[D + tid];
        sGa[tid] = hgam[tid];
        sBe[tid] = hbet[tid];
    }
    const int base = blockIdx.x * 64;
    const int cnt = min(64, Nn - base);
    __syncthreads();
    for (int idx = tid; idx < cnt * D; idx += 224) {
        size_t gi = (size_t)base * D + idx;
        float v = g_h[gi];
        if (fuse) {
            int r = idx / D;
            int c = idx - r * D;
            float hr = g_hraw[gi];
            v += fmaxf((hr - sMu[c]) * sRs[c] * sGa[c] + sBe[c], 0.f);
            g_h[gi] = v;
        }
        sX[idx] = v;
    }
    if (cnt < 64)
        for (int idx = cnt * D + tid; idx < 64 * D; idx += 224) sX[idx] = 0.f;

    const float* Ws[4] = {WA, WB, WD, WE};
    const float* bs[4] = {bA, bB, bD, bE};
    float* outs[4] = {g_A, g_B, g_Dh, g_Eh};

    const int c0 = tx * 5, r0 = ty * 4;
    for (int m = 0; m < 4; m++) {
        __syncthreads();
        for (int i = tid; i < D * D; i += 224) sW[i] = Ws[m][i];
        if (tid < D) sb[tid] = bs[m][tid];
        __syncthreads();

        float acc[4][5];
#pragma unroll
        for (int r = 0; r < 4; r++)
#pragma unroll
            for (int c = 0; c < 5; c++) acc[r][c] = sb[c0 + c];

#pragma unroll 2
        for (int k = 0; k < D; k++) {
            float w0 = sW[k * D + c0 + 0], w1 = sW[k * D + c0 + 1], w2 = sW[k * D + c0 + 2];
            float w3 = sW[k * D + c0 + 3], w4 = sW[k * D + c0 + 4];
#pragma unroll
            for (int r = 0; r < 4; r++) {
                float xv = sX[(r0 + r) * D + k];
                acc[r][0] += xv * w0; acc[r][1] += xv * w1; acc[r][2] += xv * w2;
                acc[r][3] += xv * w3; acc[r][4] += xv * w4;
            }
        }
        float* out = outs[m];
#pragma unroll
        for (int r = 0; r < 4; r++) {
            int row = base + r0 + r;
            if (row < Nn) {
#pragma unroll
                for (int c = 0; c < 5; c++) out[(size_t)row * D + c0 + c] = acc[r][c];
            }
        }
    }
}

// ---------------- streaming edge GEMM: ce = S_new@WC + ef*u + v ----------------
template <int FIRST, int WRITE_S>
__global__ __launch_bounds__(224) void edgegemm_kernel(
    const float* __restrict__ WC,
    const float* __restrict__ egam, const float* __restrict__ ebet, int E_) {
    extern __shared__ __align__(16) float dsm[];
    float* sW = dsm;             // 70*70
    float* sX = dsm + D * D;     // 128*70
    __shared__ float sef[128];
    __shared__ float su[D], sv[D], sMu[D], sRs[D], sGa[D], sBe[D];
    const int tx = threadIdx.x, ty = threadIdx.y;
    const int tid = ty * 14 + tx;
    for (int i = tid; i < D * D; i += 224) sW[i] = WC[i];
    if (tid < D) {
        su[tid] = g_u[tid];
        sv[tid] = g_v[tid];
        sMu[tid] = g_norm[2 * D + tid];
        sRs[tid] = g_norm[3 * D + tid];
        sGa[tid] = egam[tid];
        sBe[tid] = ebet[tid];
    }
    __syncthreads();

    const int base = blockIdx.x * 128;
    const int cnt = min(128, E_ - base);
    for (int idx = tid; idx < cnt * D; idx += 224) {
        size_t gi = (size_t)base * D + idx;
        int r = idx / D;
        int c = idx - r * D;
        float R = fmaxf((g_enew[gi] - sMu[c]) * sRs[c] * sGa[c] + sBe[c], 0.f);
        float Sv = FIRST ? R : (g_S[gi] + R);
        sX[idx] = Sv;
        if (WRITE_S) g_S[gi] = Sv;
    }
    if (cnt < 128)
        for (int idx = cnt * D + tid; idx < 128 * D; idx += 224) sX[idx] = 0.f;
    for (int i = tid; i < 128; i += 224) sef[i] = (i < cnt) ? g_pef[base + i] : 0.f;
    __syncthreads();

    const int c0 = tx * 5, r0 = ty * 8;
    float acc[8][5];
#pragma unroll
    for (int r = 0; r < 8; r++) {
        float efv = sef[r0 + r];
#pragma unroll
        for (int c = 0; c < 5; c++) acc[r][c] = sv[c0 + c] + efv * su[c0 + c];
    }

#pragma unroll 2
    for (int k = 0; k < D; k++) {
        float w0 = sW[k * D + c0 + 0], w1 = sW[k * D + c0 + 1], w2 = sW[k * D + c0 + 2];
        float w3 = sW[k * D + c0 + 3], w4 = sW[k * D + c0 + 4];
#pragma unroll
        for (int r = 0; r < 8; r++) {
            float xv = sX[(r0 + r) * D + k];
            acc[r][0] += xv * w0; acc[r][1] += xv * w1; acc[r][2] += xv * w2;
            acc[r][3] += xv * w3; acc[r][4] += xv * w4;
        }
    }
#pragma unroll
    for (int r = 0; r < 8; r++) {
        int ei = base + r0 + r;
        if (ei < E_) {
#pragma unroll
            for (int c = 0; c < 5; c++) g_ce[(size_t)ei * D + c0 + c] = acc[r][c];
        }
    }
}

// ---------------- node aggregation: warp-per-node, 3 cols/lane, no global hotspot ----------------
template <int RANK1, int LAST>
__global__ __launch_bounds__(256) void agg_kernel(const float* __restrict__ snorm_n, int Nn) {
    const int lane = threadIdx.x & 31;
    const int w = threadIdx.x >> 5;        // 0..7
    const int n = blockIdx.x * 8 + w;

    // reset scatter cursors for next graph replay
    { int i = blockIdx.x * 256 + threadIdx.x; if (i < Nn) g_cnt_n[i] = 0; }

    __shared__ float sStat[4][D];
    for (int i = threadIdx.x; i < 4 * D; i += 256) ((float*)sStat)[i] = 0.f;
    __syncthreads();

    const int j0 = lane, j1 = lane + 32;
    const bool m2 = lane < (D - 64);
    const int j2 = m2 ? lane + 64 : lane;

    if (n < Nn) {
        float u0, v0, u1, v1, u2, v2;
        if (RANK1) {
            u0 = g_u[j0]; v0 = g_v[j0];
            u1 = g_u[j1]; v1 = g_v[j1];
            u2 = g_u[j2]; v2 = g_v[j2];
        }
        const size_t nb = (size_t)n * D;
        const float eh0 = g_Eh[nb + j0], eh1 = g_Eh[nb + j1], eh2 = g_Eh[nb + j2];
        const int e0 = g_rowoff[n], e1 = g_rowoff[n + 1];
        float num0 = 0, den0 = 0, num1 = 0, den1 = 0, num2 = 0, den2 = 0;
        float lsE0 = 0, lqE0 = 0, lsE1 = 0, lqE1 = 0, lsE2 = 0, lqE2 = 0;
        for (int e = e0; e < e1; e++) {
            int s = g_psrc[e];
            size_t sb = (size_t)s * D;
            size_t eb = (size_t)e * D;
            float ce0, ce1, ce2;
            if (RANK1) {
                float ef = g_pef[e];
                ce0 = ef * u0 + v0; ce1 = ef * u1 + v1; ce2 = ef * u2 + v2;
            } else {
                ce0 = g_ce[eb + j0]; ce1 = g_ce[eb + j1]; ce2 = g_ce[eb + j2];
            }
            float dh0 = g_Dh[sb + j0], dh1 = g_Dh[sb + j1], dh2 = g_Dh[sb + j2];
            float bb0 = g_B[sb + j0], bb1 = g_B[sb + j1], bb2 = g_B[sb + j2];
            float en0 = ce0 + dh0 + eh0;
            float en1 = ce1 + dh1 + eh1;
            float en2 = ce2 + dh2 + eh2;
            float sg0 = 1.f / (1.f + __expf(-en0));
            float sg1 = 1.f / (1.f + __expf(-en1));
            float sg2 = 1.f / (1.f + __expf(-en2));
            num0 += bb0 * sg0; den0 += sg0;
            num1 += bb1 * sg1; den1 += sg1;
            num2 += bb2 * sg2; den2 += sg2;
            if (!LAST) {
                float sn = g_psn[e];
                float s0 = en0 * sn, s1 = en1 * sn, s2 = en2 * sn;
                g_enew[eb + j0] = s0;
                g_enew[eb + j1] = s1;
                if (m2) g_enew[eb + j2] = s2;
                lsE0 += s0; lqE0 += s0 * s0;
                lsE1 += s1; lqE1 += s1 * s1;
                lsE2 += s2; lqE2 += s2 * s2;
            }
        }
        float snn = snorm_n[n];
        float hv0 = (g_A[nb + j0] + num0 / (den0 + 1e-6f)) * snn;
        float hv1 = (g_A[nb + j1] + num1 / (den1 + 1e-6f)) * snn;
        float hv2 = (g_A[nb + j2] + num2 / (den2 + 1e-6f)) * snn;
        g_hraw[nb + j0] = hv0;
        g_hraw[nb + j1] = hv1;
        if (m2) g_hraw[nb + j2] = hv2;
        atomicAdd(&sStat[0][j0], hv0); atomicAdd(&sStat[1][j0], hv0 * hv0);
        atomicAdd(&sStat[0][j1], hv1); atomicAdd(&sStat[1][j1], hv1 * hv1);
        if (m2) { atomicAdd(&sStat[0][j2], hv2); atomicAdd(&sStat[1][j2], hv2 * hv2); }
        if (!LAST) {
            atomicAdd(&sStat[2][j0], lsE0); atomicAdd(&sStat[3][j0], lqE0);
            atomicAdd(&sStat[2][j1], lsE1); atomicAdd(&sStat[3][j1], lqE1);
            if (m2) { atomicAdd(&sStat[2][j2], lsE2); atomicAdd(&sStat[3][j2], lqE2); }
        }
    }
    __syncthreads();
    const int slot = blockIdx.x & 63;
    const int lim = LAST ? 2 * D : 4 * D;
    for (int i = threadIdx.x; i < lim; i += 256) {
        int st = i / D, j = i - st * D;
        atomicAdd(&g_statsf[st][slot][j], sStat[st][j]);
    }
}

// ---------------- finalize: reduce 64 stat shards -> norms; compute next layer's u,v ----------------
__global__ void finalize_kernel(const float* __restrict__ WembE, const float* __restrict__ bembE,
                                const float* __restrict__ WCn, const float* __restrict__ bCn,
                                int Nn, int E_, int haveE) {
    int t = threadIdx.x;  // 140 threads
    if (t < D) {
        float sh = 0.f, sq = 0.f;
        for (int s = 0; s < 64; s++) {
            sh += g_statsf[0][s][t]; g_statsf[0][s][t] = 0.f;
            sq += g_statsf[1][s][t]; g_statsf[1][s][t] = 0.f;
        }
        float mu = sh / Nn;
        float var = sq / Nn - mu * mu;
        g_norm[t] = mu;
        g_norm[D + t] = rsqrtf(fmaxf(var, 0.f) + 1e-5f);
        if (WCn) {
            float u = 0.f, v = 0.f;
            for (int k = 0; k < D; k++) {
                float w = WCn[k * D + t];
                u += WembE[k] * w;
                v += bembE[k] * w;
            }
            g_u[t] = u;
            g_v[t] = v + bCn[t];
        }
    } else if (t < 2 * D && haveE) {
        int j = t - D;
        float se = 0.f, sq = 0.f;
        for (int s = 0; s < 64; s++) {
            se += g_statsf[2][s][j]; g_statsf[2][s][j] = 0.f;
            sq += g_statsf[3][s][j]; g_statsf[3][s][j] = 0.f;
        }
        float mu = se / E_;
        float var = sq / E_ - mu * mu;
        g_norm[2 * D + j] = mu;
        g_norm[3 * D + j] = rsqrtf(fmaxf(var, 0.f) + 1e-5f);
    }
}

// ---------------- readout ----------------
__global__ void zero_readout_kernel() {
    int i = blockIdx.x * blockDim.x + threadIdx.x;
    if (i < GG * D) g_hg[i] = 0.f;
    if (i < GG) g_cnt[i] = 0.f;
}

__global__ void scatter_kernel(const int* __restrict__ gid,
                               const float* __restrict__ hgam, const float* __restrict__ hbet,
                               int Nn) {
    int j = threadIdx.x;
    float mu = g_norm[j], rs = g_norm[D + j], ga = hgam[j], bb = hbet[j];
    for (int row = blockIdx.x * 8 + threadIdx.y; row < Nn; row += gridDim.x * 8) {
        size_t idx = (size_t)row * D + j;
        float v = g_h[idx] + fmaxf((g_hraw[idx] - mu) * rs * ga + bb, 0.f);
        int g = gid[row];
        atomicAdd(&g_hg[g * D + j], v);
        if (j == 0) atomicAdd(&g_cnt[g], 1.f);
    }
}

__global__ void mlp_kernel(const float* __restrict__ W0, const float* __restrict__ b0,
                           const float* __restrict__ W1, const float* __restrict__ b1,
                           const float* __restrict__ W2, const float* __restrict__ b2,
                           float* __restrict__ out) {
    int g = threadIdx.x;
    if (g >= GG) return;
    float cnt = fmaxf(g_cnt[g], 1.f);
    float x[D];
#pragma unroll
    for (int k = 0; k < D; k++) x[k] = g_hg[g * D + k] / cnt;
    float y0[35];
#pragma unroll
    for (int o = 0; o < 35; o++) {
        float s = b0[o];
#pragma unroll
        for (int k = 0; k < D; k++) s += x[k] * W0[k * 35 + o];
        y0[o] = fmaxf(s, 0.f);
    }
    float y1[17];
#pragma unroll
    for (int o = 0; o < 17; o++) {
        float s = b1[o];
#pragma unroll
        for (int k = 0; k < 35; k++) s += y0[k] * W1[k * 17 + o];
        y1[o] = fmaxf(s, 0.f);
    }
#pragma unroll
    for (int o = 0; o < 10; o++) {
        float s = b2[o];
#pragma unroll
        for (int k = 0; k < 17; k++) s += y1[k] * W2[k * 10 + o];
        out[g * 10 + o] = s;
    }
}

// ---------------- host ----------------
extern "C" void kernel_launch(void* const* d_in, const int* in_sizes, int n_in,
                              void* d_out, int out_size) {
    const float* nodes   = (const float*)d_in[0];
    const float* ef      = (const float*)d_in[1];
    const float* snorm_n = (const float*)d_in[2];
    const float* snorm_e = (const float*)d_in[3];
    const int N = in_sizes[2];
    const int E_ = in_sizes[3];

    const int *src, *dst, *gid;
    const float *Wemb_h, *bemb_h, *Wemb_e, *bemb_e;
    const float *WA, *bA, *WB, *bB, *WC, *bC, *WDl, *bDl, *WEl, *bEl;
    const float *gh, *bh, *ge, *be, *W0, *b0, *W1, *b1, *W2, *b2;

    if (in_sizes[4] == E_) {
        src = (const int*)d_in[4]; dst = (const int*)d_in[5]; gid = (const int*)d_in[6];
        Wemb_h = (const float*)d_in[7];  bemb_h = (const float*)d_in[8];
        Wemb_e = (const float*)d_in[9];  bemb_e = (const float*)d_in[10];
        WA = (const float*)d_in[11]; bA = (const float*)d_in[12];
        WB = (const float*)d_in[13]; bB = (const float*)d_in[14];
        WC = (const float*)d_in[15]; bC = (const float*)d_in[16];
        WDl = (const float*)d_in[17]; bDl = (const float*)d_in[18];
        WEl = (const float*)d_in[19]; bEl = (const float*)d_in[20];
        gh = (const float*)d_in[21]; bh = (const float*)d_in[22];
        ge = (const float*)d_in[23]; be = (const float*)d_in[24];
        W0 = (const float*)d_in[25]; b0 = (const float*)d_in[26];
        W1 = (const float*)d_in[27]; b1 = (const float*)d_in[28];
        W2 = (const float*)d_in[29]; b2 = (const float*)d_in[30];
    } else {
        Wemb_h = (const float*)d_in[4];  bemb_h = (const float*)d_in[5];
        Wemb_e = (const float*)d_in[6];  bemb_e = (const float*)d_in[7];
        WA = (const float*)d_in[8];  bA = (const float*)d_in[9];
        WB = (const float*)d_in[10]; bB = (const float*)d_in[11];
        WC = (const float*)d_in[12]; bC = (const float*)d_in[13];
        WDl = (const float*)d_in[14]; bDl = (const float*)d_in[15];
        WEl = (const float*)d_in[16]; bEl = (const float*)d_in[17];
        gh = (const float*)d_in[18]; bh = (const float*)d_in[19];
        ge = (const float*)d_in[20]; be = (const float*)d_in[21];
        W0 = (const float*)d_in[22]; b0 = (const float*)d_in[23];
        W1 = (const float*)d_in[24]; b1 = (const float*)d_in[25];
        W2 = (const float*)d_in[26]; b2 = (const float*)d_in[27];
        src = (const int*)d_in[28]; dst = (const int*)d_in[29]; gid = (const int*)d_in[30];
    }
    float* out = (float*)d_out;

    float* ph;
    cudaGetSymbolAddress((void**)&ph, g_h);

    dim3 tb(14, 16);
    const int gemmBlocks = (N + 63) / 64;
    const int aggBlocks = (N + 7) / 8;
    const size_t smem146 = (size_t)(146 * D + 64 * 146) * sizeof(float);
    const size_t smemEG = (size_t)(D * D + 128 * D) * sizeof(float);
    cudaFuncSetAttribute(gemm70_kernel<146>, cudaFuncAttributeMaxDynamicSharedMemorySize, (int)smem146);
    cudaFuncSetAttribute(edgegemm_kernel<1, 1>, cudaFuncAttributeMaxDynamicSharedMemorySize, (int)smemEG);
    cudaFuncSetAttribute(edgegemm_kernel<0, 1>, cudaFuncAttributeMaxDynamicSharedMemorySize, (int)smemEG);
    cudaFuncSetAttribute(edgegemm_kernel<0, 0>, cudaFuncAttributeMaxDynamicSharedMemorySize, (int)smemEG);

    const int egBlocks = (E_ + 127) / 128;

    hist_kernel<<<(E_ + 255) / 256, 256>>>(dst, E_);                                    // 1
    gemm70_kernel<146><<<gemmBlocks, tb, smem146>>>(nodes, Wemb_h, bemb_h, ph, N);      // 2
    scan_kernel<<<1, 1024>>>(N, E_);                                                    // 3
    gemm4_kernel<<<gemmBlocks, tb>>>(WA, bA, WB, bB, WDl, bDl, WEl, bEl,                // 4
                                     nullptr, nullptr, 0, N);
    scatter_sort_kernel<<<(E_ + 255) / 256, 256>>>(src, dst, ef, snorm_e, E_);          // 5
    uv_kernel<<<1, D>>>(Wemb_e, bemb_e, WC, bC);                                        // 6 (layer-0 u,v)
    agg_kernel<1, 0><<<aggBlocks, 256>>>(snorm_n, N);                                   // 7
    finalize_kernel<<<1, 2 * D>>>(Wemb_e, bemb_e, WC + 1 * D * D, bC + 1 * D, N, E_, 1);// 8 (+u,v for l=1)

    for (int l = 1; l < 4; l++) {
        const float* wA = WA + l * D * D; const float* biA = bA + l * D;
        const float* wB = WB + l * D * D; const float* biB = bB + l * D;
        const float* wC = WC + l * D * D; const float* biC = bC + l * D;
        const float* wD = WDl + l * D * D; const float* biD = bDl + l * D;
        const float* wE = WEl + l * D * D; const float* biE = bEl + l * D;

        gemm4_kernel<<<gemmBlocks, tb>>>(wA, biA, wB, biB, wD, biD, wE, biE,
                                         gh + (l - 1) * D, bh + (l - 1) * D, 1, N);

        const float* eg = ge + (l - 1) * D;
        const float* eb = be + (l - 1) * D;
        if (l == 1)
            edgegemm_kernel<1, 1><<<egBlocks, tb, smemEG>>>(wC, eg, eb, E_);
        else if (l == 2)
            edgegemm_kernel<0, 1><<<egBlocks, tb, smemEG>>>(wC, eg, eb, E_);
        else
            edgegemm_kernel<0, 0><<<egBlocks, tb, smemEG>>>(wC, eg, eb, E_);

        if (l == 3) {
            agg_kernel<0, 1><<<aggBlocks, 256>>>(snorm_n, N);
            finalize_kernel<<<1, 2 * D>>>(Wemb_e, bemb_e, nullptr, nullptr, N, E_, 0);
        } else {
            agg_kernel<0, 0><<<aggBlocks, 256>>>(snorm_n, N);
            finalize_kernel<<<1, 2 * D>>>(Wemb_e, bemb_e, WC + (l + 1) * D * D,
                                          bC + (l + 1) * D, N, E_, 1);
        }
    }

    // readout (final h-update fused into scatter)
    zero_readout_kernel<<<(GG * D + 255) / 256, 256>>>();
    scatter_kernel<<<(N + 7) / 8, dim3(D, 8)>>>(gid, gh + 3 * D, bh + 3 * D, N);
    mlp_kernel<<<1, GG>>>(W0, b0, W1, b1, W2, b2, out);
}